// round 4
// baseline (speedup 1.0000x reference)
#include <cuda.h>
#include <cuda_runtime.h>
#include <cuda_fp16.h>
#include <cstdint>

// ---------------------------------------------------------------------------
// out[16384,3072] = x[16384,1024] @ W_eff^T + b
// W_eff = W_qkv; rows[0:1024) += W_b_q@W_a_q; rows[2048:3072) += W_b_v@W_a_v
// Fold LoRA into weights (fp32), convert x & W_eff to fp16, one GEMM.
// Dual path: tcgen05 (sm_103a SASS) / mma.sync+ldmatrix fallback (sm_103).
// ---------------------------------------------------------------------------

#define M_TOTAL 16384
#define N_TOTAL 3072
#define K_TOTAL 1024
#define TILE_M 128
#define TILE_N 128
#define KCHUNK 64                       // fp16 elems per stage = 128B (SW128 row)
#define NKIT   (K_TOTAL / KCHUNK)       // 16
#define NST    3
#define A_STAGE 16384                   // TILE_M * 128B
#define B_STAGE 16384                   // TILE_N * 128B

#define SMEM_TMEM  0
#define SMEM_FULL  16                   // 3 x 8B
#define SMEM_EMPTY 48                   // 3 x 8B
#define SMEM_DONE  72
#define SMEM_BIAS  128                  // 128 floats
#define SMEM_A     1024
#define SMEM_B     (SMEM_A + NST * A_STAGE)     // 50176
#define SMEM_TOTAL (SMEM_B + NST * B_STAGE)     // 99328 -> 2 CTAs/SM

#if defined(__CUDA_ARCH__) && defined(__CUDA_ARCH_FEAT_SM103_ALL)
#define USE_TC 1
#else
#define USE_TC 0
#endif

// idesc kind::f16: dtype=F32 (bit4), N>>3 @[17:22], M>>4 @[24:28]
#define MMA_IDESC ((1u << 4) | ((TILE_N / 8) << 17) | ((TILE_M / 16) << 24))

// fp16 scratch (static device arrays are allowed; cudaMalloc is not)
__device__ __align__(1024) __half g_xh[(size_t)M_TOTAL * K_TOTAL];
__device__ __align__(1024) __half g_wh[(size_t)N_TOTAL * K_TOTAL];

// ---------------------------------------------------------------------------
// Common PTX helpers (all plain sm_90-level, compile at compute_103)
// ---------------------------------------------------------------------------
__device__ __forceinline__ uint32_t smem_u32(const void* p) {
    uint32_t a;
    asm("{ .reg .u64 t; cvta.to.shared.u64 t, %1; cvt.u32.u64 %0, t; }"
        : "=r"(a) : "l"(p));
    return a;
}
__device__ __forceinline__ uint32_t elect_one() {
    uint32_t pred;
    asm volatile(
        "{\n\t.reg .pred p;\n\telect.sync _|p, 0xFFFFFFFF;\n\t"
        "selp.b32 %0, 1, 0, p;\n\t}" : "=r"(pred));
    return pred;
}
__device__ __forceinline__ void mbar_init(uint32_t m, uint32_t c) {
    asm volatile("mbarrier.init.shared.b64 [%0], %1;" :: "r"(m), "r"(c) : "memory");
}
__device__ __forceinline__ void mbar_expect_tx(uint32_t m, uint32_t bytes) {
    asm volatile("mbarrier.arrive.expect_tx.shared.b64 _, [%0], %1;"
                 :: "r"(m), "r"(bytes) : "memory");
}
__device__ __forceinline__ void mbar_arrive(uint32_t m) {
    asm volatile("mbarrier.arrive.shared.b64 _, [%0];" :: "r"(m) : "memory");
}
__device__ __forceinline__ void mbar_wait(uint32_t m, uint32_t phase) {
    uint32_t done = 0;
    while (!done) {
        asm volatile(
            "{\n\t.reg .pred p;\n\t"
            "mbarrier.try_wait.parity.acquire.cta.shared::cta.b64 p, [%1], %2, 0x989680;\n\t"
            "selp.b32 %0, 1, 0, p;\n\t}"
            : "=r"(done) : "r"(m), "r"(phase) : "memory");
    }
}
__device__ __forceinline__ void tma_load_2d(uint32_t dst, const void* map,
                                            int cx, int cy, uint32_t mbar) {
    asm volatile(
        "cp.async.bulk.tensor.2d.shared::cta.global.tile.mbarrier::complete_tx::bytes "
        "[%0], [%1, {%2, %3}], [%4];"
        :: "r"(dst), "l"(map), "r"(cx), "r"(cy), "r"(mbar) : "memory");
}

// Fallback-path primitives (sm_80-level)
__device__ __forceinline__ void ldsm_x4(uint32_t* r, uint32_t addr) {
    asm volatile("ldmatrix.sync.aligned.m8n8.x4.shared.b16 {%0,%1,%2,%3}, [%4];"
                 : "=r"(r[0]), "=r"(r[1]), "=r"(r[2]), "=r"(r[3]) : "r"(addr));
}
__device__ __forceinline__ void mma16816(float* c, const uint32_t* a,
                                         const uint32_t* b) {
    asm volatile(
        "mma.sync.aligned.m16n8k16.row.col.f32.f16.f16.f32 "
        "{%0,%1,%2,%3}, {%4,%5,%6,%7}, {%8,%9}, {%0,%1,%2,%3};"
        : "+f"(c[0]), "+f"(c[1]), "+f"(c[2]), "+f"(c[3])
        : "r"(a[0]), "r"(a[1]), "r"(a[2]), "r"(a[3]), "r"(b[0]), "r"(b[1]));
}

#if USE_TC
// tcgen05 helpers — only emitted when targeting sm_103a
__device__ __forceinline__ uint64_t make_desc_sw128(uint32_t addr) {
    return ((uint64_t)2 << 61) | ((uint64_t)1 << 46) | ((uint64_t)64 << 32) |
           ((uint64_t)1 << 16) | (uint64_t)((addr >> 4) & 0x3FFF);
}
__device__ __forceinline__ void mma_f16_ss(uint32_t d, uint64_t ad, uint64_t bd,
                                           uint32_t en) {
    asm volatile(
        "{\n\t.reg .pred p;\n\tsetp.ne.u32 p, %5, 0;\n\t"
        "tcgen05.mma.cta_group::1.kind::f16 [%0], %1, %2, %3, {%4, %4, %4, %4}, p;\n\t}"
        :: "r"(d), "l"(ad), "l"(bd), "r"(MMA_IDESC), "r"(0u), "r"(en) : "memory");
}
__device__ __forceinline__ void tc_commit(uint32_t mbar) {
    asm volatile(
        "tcgen05.commit.cta_group::1.mbarrier::arrive::one.shared::cluster.b64 [%0];"
        :: "r"(mbar) : "memory");
}
__device__ __forceinline__ void tc_alloc(uint32_t smem_dst, uint32_t ncols) {
    asm volatile("tcgen05.alloc.cta_group::1.sync.aligned.shared::cta.b32 [%0], %1;"
                 :: "r"(smem_dst), "r"(ncols) : "memory");
}
__device__ __forceinline__ void tc_dealloc(uint32_t tmem, uint32_t ncols) {
    asm volatile("tcgen05.dealloc.cta_group::1.sync.aligned.b32 %0, %1;"
                 :: "r"(tmem), "r"(ncols));
}
__device__ __forceinline__ void tc_relinquish() {
    asm volatile("tcgen05.relinquish_alloc_permit.cta_group::1.sync.aligned;");
}
__device__ __forceinline__ void tc_fence_after() {
    asm volatile("tcgen05.fence::after_thread_sync;" ::: "memory");
}
__device__ __forceinline__ void tc_wait_ld() {
    asm volatile("tcgen05.wait::ld.sync.aligned;" ::: "memory");
}
__device__ __forceinline__ void tc_ld_x32(uint32_t* r, uint32_t tmem) {
    asm volatile(
        "tcgen05.ld.sync.aligned.32x32b.x32.b32 "
        "{%0, %1, %2, %3, %4, %5, %6, %7, %8, %9, %10, %11, %12, %13, %14, %15, "
        " %16, %17, %18, %19, %20, %21, %22, %23, %24, %25, %26, %27, %28, %29, %30, %31}, [%32];"
        : "=r"(r[0]), "=r"(r[1]), "=r"(r[2]), "=r"(r[3]), "=r"(r[4]), "=r"(r[5]),
          "=r"(r[6]), "=r"(r[7]), "=r"(r[8]), "=r"(r[9]), "=r"(r[10]), "=r"(r[11]),
          "=r"(r[12]), "=r"(r[13]), "=r"(r[14]), "=r"(r[15]), "=r"(r[16]), "=r"(r[17]),
          "=r"(r[18]), "=r"(r[19]), "=r"(r[20]), "=r"(r[21]), "=r"(r[22]), "=r"(r[23]),
          "=r"(r[24]), "=r"(r[25]), "=r"(r[26]), "=r"(r[27]), "=r"(r[28]), "=r"(r[29]),
          "=r"(r[30]), "=r"(r[31])
        : "r"(tmem));
}
#endif  // USE_TC

// ---------------------------------------------------------------------------
// Pre-kernel 1: x fp32 -> fp16
// ---------------------------------------------------------------------------
__global__ void conv_x_kernel(const float4* __restrict__ x) {
    int i = blockIdx.x * blockDim.x + threadIdx.x;   // exactly M*K/4 threads
    float4 v = x[i];
    __half2* o = reinterpret_cast<__half2*>(g_xh);
    o[2 * i + 0] = __floats2half2_rn(v.x, v.y);
    o[2 * i + 1] = __floats2half2_rn(v.z, v.w);
}

// ---------------------------------------------------------------------------
// Pre-kernel 2: W_eff = W_qkv + LoRA folds (fp32 math) -> fp16
// ---------------------------------------------------------------------------
__global__ void fuse_w_kernel(const float* __restrict__ Wqkv,
                              const float* __restrict__ Waq,
                              const float* __restrict__ Wbq,
                              const float* __restrict__ Wav,
                              const float* __restrict__ Wbv) {
    int idx = blockIdx.x * 256 + threadIdx.x;        // exactly N*K threads
    int n = idx >> 10;
    int k = idx & 1023;
    float acc = Wqkv[idx];
    if (n < 1024) {
#pragma unroll
        for (int r = 0; r < 16; ++r) acc += Wbq[n * 16 + r] * Waq[r * 1024 + k];
    } else if (n >= 2048) {
        int nn = n - 2048;
#pragma unroll
        for (int r = 0; r < 16; ++r) acc += Wbv[nn * 16 + r] * Wav[r * 1024 + k];
    }
    g_wh[idx] = __float2half_rn(acc);
}

// ---------------------------------------------------------------------------
// Main GEMM: 128x128 tile, 3-stage TMA pipeline, 9 warps (8 compute + 1 TMA)
// grid = (N/128, M/128) = (24, 128)
// ---------------------------------------------------------------------------
__global__ void __launch_bounds__(288, 2)
gemm_f16_kernel(const __grid_constant__ CUtensorMap tmA,
                const __grid_constant__ CUtensorMap tmB,
                const float* __restrict__ bias,
                float* __restrict__ out) {
    extern __shared__ __align__(1024) char smem[];
    const uint32_t sb = smem_u32(smem);
    const int tid = threadIdx.x;
    const int wid = tid >> 5;
    const int lid = tid & 31;
    const int n_base = blockIdx.x * TILE_N;
    const int m_base = blockIdx.y * TILE_M;

#if USE_TC
    if (wid == 0) tc_alloc(sb + SMEM_TMEM, 128);
#endif
    if (tid == 0) {
#pragma unroll
        for (int s = 0; s < NST; ++s) {
            mbar_init(sb + SMEM_FULL + s * 8, 1);
            mbar_init(sb + SMEM_EMPTY + s * 8, USE_TC ? 1 : 8);
        }
        mbar_init(sb + SMEM_DONE, 1);
    }
    float* sh_bias = reinterpret_cast<float*>(smem + SMEM_BIAS);
    if (tid < TILE_N) sh_bias[tid] = bias[n_base + tid];
    __syncthreads();

    // ---- producer: warp 8, one elected lane ----
    if (wid == 8) {
        if (elect_one()) {
            int s = 0, ph = 1;                      // phase 1: first waits pass
            for (int kt = 0; kt < NKIT; ++kt) {
                mbar_wait(sb + SMEM_EMPTY + s * 8, ph);
                mbar_expect_tx(sb + SMEM_FULL + s * 8, A_STAGE + B_STAGE);
                tma_load_2d(sb + SMEM_A + s * A_STAGE, &tmA, kt * KCHUNK, m_base,
                            sb + SMEM_FULL + s * 8);
                tma_load_2d(sb + SMEM_B + s * B_STAGE, &tmB, kt * KCHUNK, n_base,
                            sb + SMEM_FULL + s * 8);
                if (++s == NST) { s = 0; ph ^= 1; }
            }
        }
    }

#if USE_TC
    // ================= tcgen05 path =================
    uint32_t tmem;
    asm volatile("ld.shared.b32 %0, [%1];" : "=r"(tmem) : "r"(sb + SMEM_TMEM));
    if (wid == 0) tc_relinquish();

    if (wid == 0 && elect_one()) {
        int s = 0, ph = 0;
        for (int kt = 0; kt < NKIT; ++kt) {
            mbar_wait(sb + SMEM_FULL + s * 8, ph);
            uint64_t ad = make_desc_sw128(sb + SMEM_A + s * A_STAGE);
            uint64_t bd = make_desc_sw128(sb + SMEM_B + s * B_STAGE);
#pragma unroll
            for (int j = 0; j < 4; ++j)
                mma_f16_ss(tmem, ad + j * 2, bd + j * 2, (kt | j) != 0);
            tc_commit(sb + SMEM_EMPTY + s * 8);
            if (++s == NST) { s = 0; ph ^= 1; }
        }
        tc_commit(sb + SMEM_DONE);
    }

    mbar_wait(sb + SMEM_DONE, 0);
    tc_fence_after();

    if (wid < 8) {
        // warp w: TMEM rows (w&3)*32+lid, cols (w>>2)*64 .. +63
        const int colblk = (wid >> 2) * 64;
        float* orow = out + (size_t)(m_base + (wid & 3) * 32 + lid) * N_TOTAL +
                      n_base + colblk;
        uint32_t r[64];
        tc_ld_x32(r, tmem + colblk);
        tc_ld_x32(r + 32, tmem + colblk + 32);
        tc_wait_ld();
#pragma unroll
        for (int c = 0; c < 64; c += 4) {
            float4 v;
            v.x = __uint_as_float(r[c + 0]) + sh_bias[colblk + c + 0];
            v.y = __uint_as_float(r[c + 1]) + sh_bias[colblk + c + 1];
            v.z = __uint_as_float(r[c + 2]) + sh_bias[colblk + c + 2];
            v.w = __uint_as_float(r[c + 3]) + sh_bias[colblk + c + 3];
            *reinterpret_cast<float4*>(orow + c) = v;
        }
    }
    __syncthreads();
    if (wid == 0) tc_dealloc(tmem, 128);

#else
    // ================= mma.sync fallback path =================
    if (wid < 8) {
        const int warp_m = wid & 3;       // 4 x 2 warp grid
        const int warp_n = wid >> 2;
        const int grp = lid >> 3;
        const int lr = lid & 7;

        float acc[2][8][4];
#pragma unroll
        for (int mt = 0; mt < 2; ++mt)
#pragma unroll
            for (int nt = 0; nt < 8; ++nt)
#pragma unroll
                for (int q = 0; q < 4; ++q) acc[mt][nt][q] = 0.f;

        // precomputed swizzled lane offsets (within a stage) for j=0
        // A matrices: m0 rows0-7/k0-7, m1 rows8-15/k0-7, m2 r0-7/k8-15, m3 r8-15/k8-15
        uint32_t a_off[2];
#pragma unroll
        for (int mt = 0; mt < 2; ++mt) {
            int row = warp_m * 32 + mt * 16 + (grp & 1) * 8 + lr;
            int colb = (grp >> 1) * 16;
            a_off[mt] = row * 128 + (colb ^ ((row & 7) << 4));
        }
        // B matrices: m0 n0-7/k0-7, m1 n0-7/k8-15, m2 n8-15/k0-7, m3 n8-15/k8-15
        uint32_t b_off[4];
#pragma unroll
        for (int ntp = 0; ntp < 4; ++ntp) {
            int nrow = warp_n * 64 + ntp * 16 + (grp >> 1) * 8 + lr;
            int colb = (grp & 1) * 16;
            b_off[ntp] = nrow * 128 + (colb ^ ((nrow & 7) << 4));
        }

        int s = 0, ph = 0;
        for (int kt = 0; kt < NKIT; ++kt) {
            mbar_wait(sb + SMEM_FULL + s * 8, ph);
            const uint32_t aBase = sb + SMEM_A + s * A_STAGE;
            const uint32_t bBase = sb + SMEM_B + s * B_STAGE;
#pragma unroll
            for (int j = 0; j < 4; ++j) {
                const uint32_t jsw = j * 32;   // k16 step = 32 bytes, XOR-safe
                uint32_t a[2][4];
                ldsm_x4(a[0], aBase + (a_off[0] ^ jsw));
                ldsm_x4(a[1], aBase + (a_off[1] ^ jsw));
#pragma unroll
                for (int ntp = 0; ntp < 4; ++ntp) {
                    uint32_t b[4];
                    ldsm_x4(b, bBase + (b_off[ntp] ^ jsw));
                    mma16816(acc[0][2 * ntp + 0], a[0], b + 0);
                    mma16816(acc[0][2 * ntp + 1], a[0], b + 2);
                    mma16816(acc[1][2 * ntp + 0], a[1], b + 0);
                    mma16816(acc[1][2 * ntp + 1], a[1], b + 2);
                }
            }
            __syncwarp();
            if (lid == 0) mbar_arrive(sb + SMEM_EMPTY + s * 8);
            if (++s == NST) { s = 0; ph ^= 1; }
        }

        // epilogue: bias + direct stores
        float* obase = out + (size_t)(m_base + warp_m * 32) * N_TOTAL + n_base +
                       warp_n * 64;
        const int r0 = lid >> 2;
        const int c0 = (lid & 3) * 2;
#pragma unroll
        for (int mt = 0; mt < 2; ++mt) {
#pragma unroll
            for (int nt = 0; nt < 8; ++nt) {
                int col = nt * 8 + c0;
                float b0 = sh_bias[warp_n * 64 + col];
                float b1 = sh_bias[warp_n * 64 + col + 1];
                float2 v0 = {acc[mt][nt][0] + b0, acc[mt][nt][1] + b1};
                float2 v1 = {acc[mt][nt][2] + b0, acc[mt][nt][3] + b1};
                *reinterpret_cast<float2*>(obase + (size_t)(mt * 16 + r0) * N_TOTAL + col) = v0;
                *reinterpret_cast<float2*>(obase + (size_t)(mt * 16 + r0 + 8) * N_TOTAL + col) = v1;
            }
        }
    }
#endif
}

// ---------------------------------------------------------------------------
// Host
// ---------------------------------------------------------------------------
typedef CUresult (*PFN_encodeTiled)(
    CUtensorMap*, CUtensorMapDataType, cuuint32_t, void*,
    const cuuint64_t*, const cuuint64_t*, const cuuint32_t*, const cuuint32_t*,
    CUtensorMapInterleave, CUtensorMapSwizzle, CUtensorMapL2promotion,
    CUtensorMapFloatOOBfill);

extern "C" void kernel_launch(void* const* d_in, const int* in_sizes, int n_in,
                              void* d_out, int out_size) {
    const float* x    = (const float*)d_in[0];
    const float* Wqkv = (const float*)d_in[1];
    const float* bqkv = (const float*)d_in[2];
    const float* Waq  = (const float*)d_in[3];
    const float* Wbq  = (const float*)d_in[4];
    const float* Wav  = (const float*)d_in[5];
    const float* Wbv  = (const float*)d_in[6];
    float* out = (float*)d_out;

    conv_x_kernel<<<(M_TOTAL * K_TOTAL) / 4 / 256, 256>>>((const float4*)x);
    fuse_w_kernel<<<(N_TOTAL * K_TOTAL) / 256, 256>>>(Wqkv, Waq, Wbq, Wav, Wbv);

    void* xh_ptr = nullptr;
    void* wh_ptr = nullptr;
    cudaGetSymbolAddress(&xh_ptr, g_xh);
    cudaGetSymbolAddress(&wh_ptr, g_wh);

    void* fp = nullptr;
    cudaDriverEntryPointQueryResult qr;
#if CUDART_VERSION >= 12050
    cudaGetDriverEntryPointByVersion("cuTensorMapEncodeTiled", &fp, 12000,
                                     cudaEnableDefault, &qr);
#else
    cudaGetDriverEntryPoint("cuTensorMapEncodeTiled", &fp, cudaEnableDefault, &qr);
#endif
    PFN_encodeTiled encode = (PFN_encodeTiled)fp;

    CUtensorMap tmA, tmB;
    {
        cuuint64_t dims[2]   = {(cuuint64_t)K_TOTAL, (cuuint64_t)M_TOTAL};
        cuuint64_t stride[1] = {(cuuint64_t)K_TOTAL * 2};
        cuuint32_t box[2]    = {KCHUNK, TILE_M};
        cuuint32_t es[2]     = {1, 1};
        encode(&tmA, CU_TENSOR_MAP_DATA_TYPE_FLOAT16, 2, xh_ptr, dims, stride, box,
               es, CU_TENSOR_MAP_INTERLEAVE_NONE, CU_TENSOR_MAP_SWIZZLE_128B,
               CU_TENSOR_MAP_L2_PROMOTION_L2_128B, CU_TENSOR_MAP_FLOAT_OOB_FILL_NONE);
    }
    {
        cuuint64_t dims[2]   = {(cuuint64_t)K_TOTAL, (cuuint64_t)N_TOTAL};
        cuuint64_t stride[1] = {(cuuint64_t)K_TOTAL * 2};
        cuuint32_t box[2]    = {KCHUNK, TILE_N};
        cuuint32_t es[2]     = {1, 1};
        encode(&tmB, CU_TENSOR_MAP_DATA_TYPE_FLOAT16, 2, wh_ptr, dims, stride, box,
               es, CU_TENSOR_MAP_INTERLEAVE_NONE, CU_TENSOR_MAP_SWIZZLE_128B,
               CU_TENSOR_MAP_L2_PROMOTION_L2_128B, CU_TENSOR_MAP_FLOAT_OOB_FILL_NONE);
    }

    cudaFuncSetAttribute(gemm_f16_kernel,
                         cudaFuncAttributeMaxDynamicSharedMemorySize, SMEM_TOTAL);

    dim3 grid(N_TOTAL / TILE_N, M_TOTAL / TILE_M, 1);   // (24, 128)
    gemm_f16_kernel<<<grid, 288, SMEM_TOTAL>>>(tmA, tmB, bqkv, out);
}